// round 13
// baseline (speedup 1.0000x reference)
#include <cuda_runtime.h>
#include <cuda_fp16.h>
#include <cstdint>

#define M_TOTAL 65536
#define W_STRIDE 512

__device__ float g_bufA[256 * 256];
__device__ float g_bufB[256 * 256];
__device__ float g_scale[1];
__device__ unsigned g_bar;
__device__ __align__(16) __half g_whi[256 * 256];
__device__ __align__(16) __half g_wlo[256 * 256];
__device__ __align__(16) __half g_xh[(size_t)M_TOTAL * 256];

__device__ __forceinline__ float tanh_acc(float z) {
    float e = __expf(2.0f * z);
    return 1.0f - 2.0f / (e + 1.0f);
}
__device__ __forceinline__ uint32_t smem_u32(const void* p) {
    uint32_t a;
    asm("{ .reg .u64 t; cvta.to.shared.u64 t, %1; cvt.u32.u64 %0, t; }" : "=r"(a) : "l"(p));
    return a;
}
#define CP_ASYNC16(dst, src) \
    asm volatile("cp.async.cg.shared.global [%0], [%1], 16;" :: "r"(dst), "l"(src) : "memory")
#define CP_COMMIT() asm volatile("cp.async.commit_group;" ::: "memory")
#define CP_WAIT0()  asm volatile("cp.async.wait_group 0;" ::: "memory")
#define CP_WAIT1()  asm volatile("cp.async.wait_group 1;" ::: "memory")
#define LDM_X4(r0, r1, r2, r3, a) \
    asm volatile("ldmatrix.sync.aligned.m8n8.x4.shared.b16 {%0,%1,%2,%3}, [%4];" \
                 : "=r"(r0), "=r"(r1), "=r"(r2), "=r"(r3) : "r"(a))
__device__ __forceinline__ void mma16816(float* c, const uint32_t* a, const uint32_t* b) {
    asm volatile(
        "mma.sync.aligned.m16n8k16.row.col.f32.f16.f16.f32 "
        "{%0,%1,%2,%3},{%4,%5,%6,%7},{%8,%9},{%0,%1,%2,%3};"
        : "+f"(c[0]), "+f"(c[1]), "+f"(c[2]), "+f"(c[3])
        : "r"(a[0]), "r"(a[1]), "r"(a[2]), "r"(a[3]), "r"(b[0]), "r"(b[1]));
}

// ---- Kernel 1: bandwidth pass. X hi-split (CTAs 0..2047, 64B/thread),
// ---- W hi/lo split (2048..2079), ztail (2080..2179).
__global__ __launch_bounds__(256) void split_kernel(const float* __restrict__ W,
                                                    const float* __restrict__ X,
                                                    float* __restrict__ tailp, int tail_n) {
    const int cid = blockIdx.x;
    if (cid < 2048) {
        const size_t e0 = ((size_t)cid * 256 + threadIdx.x) * 32;  // 32 floats
        float4 f[8];
#pragma unroll
        for (int j = 0; j < 8; j++) f[j] = *(const float4*)(X + e0 + j * 4);  // 8 indep LDG.128
        uint4 o[4];
#pragma unroll
        for (int j = 0; j < 4; j++) {
            __half2 h0 = __floats2half2_rn(f[2 * j].x, f[2 * j].y);
            __half2 h1 = __floats2half2_rn(f[2 * j].z, f[2 * j].w);
            __half2 h2 = __floats2half2_rn(f[2 * j + 1].x, f[2 * j + 1].y);
            __half2 h3 = __floats2half2_rn(f[2 * j + 1].z, f[2 * j + 1].w);
            o[j] = make_uint4(*(uint32_t*)&h0, *(uint32_t*)&h1, *(uint32_t*)&h2, *(uint32_t*)&h3);
        }
#pragma unroll
        for (int j = 0; j < 4; j++) *(uint4*)(g_xh + e0 + j * 8) = o[j];
    } else if (cid < 2080) {
        const int e = ((cid - 2048) * 256 + threadIdx.x) * 8;
        const int r = e >> 8, c = e & 255;
        const float4 f0 = *(const float4*)(W + r * W_STRIDE + c);
        const float4 f1 = *(const float4*)(W + r * W_STRIDE + c + 4);
        const float f[8] = {f0.x, f0.y, f0.z, f0.w, f1.x, f1.y, f1.z, f1.w};
        uint32_t hi[4], lo[4];
#pragma unroll
        for (int q = 0; q < 4; q++) {
            const __half h0 = __float2half_rn(f[2 * q]);
            const __half h1 = __float2half_rn(f[2 * q + 1]);
            const __half l0 = __float2half_rn(f[2 * q] - __half2float(h0));
            const __half l1 = __float2half_rn(f[2 * q + 1] - __half2float(h1));
            hi[q] = (uint32_t)*(const uint16_t*)&h0 | ((uint32_t)*(const uint16_t*)&h1 << 16);
            lo[q] = (uint32_t)*(const uint16_t*)&l0 | ((uint32_t)*(const uint16_t*)&l1 << 16);
        }
        *(uint4*)(g_whi + e) = make_uint4(hi[0], hi[1], hi[2], hi[3]);
        *(uint4*)(g_wlo + e) = make_uint4(lo[0], lo[1], lo[2], lo[3]);
    } else {
        const int i = (cid - 2080) * 256 + threadIdx.x;
        if (i < tail_n) tailp[i] = 0.f;
    }
}

// ---- Kernel 2: sigma. 64 CTAs x 1024 thr: gram -> G^32 (grid-synced fp32
// ---- squarings) -> CTA0 scaled-fp16-SMEM powiter 16+1.  lam = s*sigma^64.
#define SIG_SMEM (131072 + 1024 + 8192 + 160)
__device__ __forceinline__ void gsync(unsigned tgt) {
    __syncthreads();
    if (threadIdx.x == 0) {
        __threadfence();
        atomicAdd(&g_bar, 1u);
        while (*(volatile unsigned*)&g_bar < tgt) {}
        __threadfence();
    }
    __syncthreads();
}
__device__ void sq1024(const float* A, float* C, float (*As)[33], float (*Bs)[33],
                       int i0, int j0, int ty, int tx) {
    float a = 0.f;
    for (int kt = 0; kt < 256; kt += 32) {
        As[ty][tx] = A[(i0 + ty) * 256 + kt + tx];
        Bs[ty][tx] = A[(j0 + ty) * 256 + kt + tx];  // symmetric
        __syncthreads();
#pragma unroll
        for (int k = 0; k < 32; k++) a = fmaf(As[ty][k], Bs[tx][k], a);
        __syncthreads();
    }
    C[(i0 + ty) * 256 + j0 + tx] = a;
}
__global__ __launch_bounds__(1024) void sigma_kernel(const float* __restrict__ W) {
    extern __shared__ char sm[];
    const int tid = threadIdx.x;
    float (*As)[33] = (float(*)[33])sm;
    float (*Bs)[33] = (float(*)[33])(sm + 4224);
    const int ty = tid >> 5, tx = tid & 31;
    const int i0 = (blockIdx.x >> 3) * 32, j0 = (blockIdx.x & 7) * 32;
    {
        float a = 0.f;
        for (int kt = 0; kt < 512; kt += 32) {
            As[ty][tx] = W[(i0 + ty) * W_STRIDE + kt + tx];
            Bs[ty][tx] = W[(j0 + ty) * W_STRIDE + kt + tx];
            __syncthreads();
#pragma unroll
            for (int k = 0; k < 32; k++) a = fmaf(As[ty][k], Bs[tx][k], a);
            __syncthreads();
        }
        g_bufA[(i0 + ty) * 256 + j0 + tx] = a;
    }
    gsync(64);
    sq1024(g_bufA, g_bufB, As, Bs, i0, j0, ty, tx);  gsync(128);  // G^2
    sq1024(g_bufB, g_bufA, As, Bs, i0, j0, ty, tx);  gsync(192);  // G^4
    sq1024(g_bufA, g_bufB, As, Bs, i0, j0, ty, tx);  gsync(256);  // G^8
    sq1024(g_bufB, g_bufA, As, Bs, i0, j0, ty, tx);  gsync(320);  // G^16
    sq1024(g_bufA, g_bufB, As, Bs, i0, j0, ty, tx);  gsync(384);  // G^32
    if (blockIdx.x != 0) return;

    __half2* H2 = (__half2*)sm;                      // 128KB
    float* v    = (float*)(sm + 131072);
    float* wq   = (float*)(sm + 131072 + 1024);
    float* red  = (float*)(sm + 131072 + 1024 + 8192);
    const int lane = tid & 31, warp = tid >> 5;
    float md = (tid < 256) ? g_bufB[tid * 257] : 0.f;  // PSD: max entry on diag
#pragma unroll
    for (int off = 16; off > 0; off >>= 1) md = fmaxf(md, __shfl_xor_sync(0xffffffffu, md, off));
    if (lane == 0) red[warp] = md;
    __syncthreads();
    if (tid == 0) {
        float m = 0.f;
        for (int k = 0; k < 8; k++) m = fmaxf(m, red[k]);
        const int kexp = 13 - ilogbf(m);
        red[33] = exp2f((float)kexp);
        red[34] = (float)kexp;
    }
    __syncthreads();
    const float s = red[33];
    for (int i = tid; i < 32768; i += 1024) {
        const float2 f = ((const float2*)g_bufB)[i];
        H2[i] = __floats2half2_rn(f.x * s, f.y * s);
    }
    if (tid < 256) v[tid] = 0.0625f;
    __syncthreads();
    const int jp = tid & 127, q = tid >> 7;
    float lam = 0.f;
    for (int it = 0; it <= 16; it++) {
        float w0 = 0.f, w1 = 0.f;
        const __half2* Hp = H2 + (q * 32) * 128 + jp;
#pragma unroll 8
        for (int ii = 0; ii < 32; ii++) {
            const float2 h = __half22float2(Hp[ii * 128]);
            const float vi = v[q * 32 + ii];
            w0 = fmaf(h.x, vi, w0);
            w1 = fmaf(h.y, vi, w1);
        }
        wq[q * 256 + 2 * jp]     = w0;
        wq[q * 256 + 2 * jp + 1] = w1;
        __syncthreads();
        float r = 0.f, ws = 0.f;
        if (tid < 256) {
#pragma unroll
            for (int k = 0; k < 8; k++) ws += wq[k * 256 + tid];
            r = (it == 16) ? ws * v[tid] : ws * ws;
        }
#pragma unroll
        for (int off = 16; off > 0; off >>= 1) r += __shfl_xor_sync(0xffffffffu, r, off);
        if (tid < 256 && lane == 0) red[tid >> 5] = r;
        __syncthreads();
        if (tid == 0) { float t2 = 0.f; for (int k = 0; k < 8; k++) t2 += red[k]; red[32] = t2; }
        __syncthreads();
        if (it == 16) { lam = red[32]; break; }
        const float inv = rsqrtf(red[32]);
        if (tid < 256) v[tid] = ws * inv;
        __syncthreads();
    }
    if (tid == 0) {
        const double kexp = (double)red[34];
        const double sigma = exp2((log2((double)lam) - kexp) / 64.0);
        g_scale[0] = (float)(1.0 / (sigma + 1e-6));
        __threadfence();
        g_bar = 0;  // reset for graph replay
    }
}

// ---- Kernel 3: GEMM (verbatim 61.8us config). 2-term split, 128x64 tile,
// ---- all cp.async, 3 stages, 3 CTA/SM, fused tanh epilogue.
#define LDHW 40
#define WH_O 10240u
#define WL_O 15360u
#define STG  20480u
#define GEMM_SMEM (3 * 20480)

__global__ __launch_bounds__(256, 3)
void gemm_mma_kernel(const float* __restrict__ bias, float* __restrict__ out) {
    extern __shared__ __align__(16) char sm[];
    const uint32_t sb = smem_u32(sm);
    const int tid = threadIdx.x;
    const int wid = tid >> 5, lane = tid & 31;
    const int g = lane >> 2, tq = lane & 3;
    const int m0 = blockIdx.y * 128, n0 = blockIdx.x * 64;
    const int wm = (wid >> 1) * 32, wn = (wid & 1) * 32;

    const int arow = tid >> 1, aseg = (tid & 1) * 16;
    const __half* xg = g_xh + (size_t)(m0 + arow) * 256 + aseg;
    const uint32_t aDst = sb + (uint32_t)(arow * LDHW + aseg) * 2;
    const int brow = tid >> 2, bseg = (tid & 3) * 8;
    const __half* wh = g_whi + (n0 + brow) * 256 + bseg;
    const __half* wl = g_wlo + (n0 + brow) * 256 + bseg;
    const uint32_t wDst = sb + (uint32_t)(brow * LDHW + bseg) * 2;

    const uint32_t aOff = (uint32_t)(((wm + (lane & 15)) * LDHW) + ((lane >> 4) * 8)) * 2;
    const uint32_t bOff = (uint32_t)(((wn + (lane & 7) + ((lane >> 4) << 3)) * LDHW) +
                                     (((lane >> 3) & 1) * 8)) * 2;

    float acc[2][4][4];
#pragma unroll
    for (int i = 0; i < 2; i++)
#pragma unroll
        for (int j = 0; j < 4; j++)
#pragma unroll
            for (int k = 0; k < 4; k++) acc[i][j][k] = 0.f;

#pragma unroll
    for (int s = 0; s < 2; s++) {
        const uint32_t stg = (uint32_t)s * STG;
        CP_ASYNC16(aDst + stg,      xg + s * 32);
        CP_ASYNC16(aDst + stg + 16, xg + s * 32 + 8);
        CP_ASYNC16(wDst + stg + WH_O, wh + s * 32);
        CP_ASYNC16(wDst + stg + WL_O, wl + s * 32);
        CP_COMMIT();
    }
    CP_WAIT1();
    __syncthreads();

    for (int c = 0; c < 8; c++) {
        const uint32_t stg = sb + (uint32_t)(c % 3) * STG;
        if (c + 2 < 8) {
            const uint32_t ns = (uint32_t)((c + 2) % 3) * STG;
            CP_ASYNC16(aDst + ns,      xg + (c + 2) * 32);
            CP_ASYNC16(aDst + ns + 16, xg + (c + 2) * 32 + 8);
            CP_ASYNC16(wDst + ns + WH_O, wh + (c + 2) * 32);
            CP_ASYNC16(wDst + ns + WL_O, wl + (c + 2) * 32);
            CP_COMMIT();
        }
#pragma unroll
        for (int ks = 0; ks < 2; ks++) {
            const uint32_t ko = (uint32_t)ks * 32;
            uint32_t aH[2][4], bH[8], bL[8];
            LDM_X4(aH[0][0], aH[0][1], aH[0][2], aH[0][3], stg + aOff + ko);
            LDM_X4(aH[1][0], aH[1][1], aH[1][2], aH[1][3], stg + aOff + ko + 16 * LDHW * 2);
            LDM_X4(bH[0], bH[1], bH[2], bH[3], stg + WH_O + bOff + ko);
            LDM_X4(bH[4], bH[5], bH[6], bH[7], stg + WH_O + bOff + ko + 16 * LDHW * 2);
            LDM_X4(bL[0], bL[1], bL[2], bL[3], stg + WL_O + bOff + ko);
            LDM_X4(bL[4], bL[5], bL[6], bL[7], stg + WL_O + bOff + ko + 16 * LDHW * 2);
#pragma unroll
            for (int nt = 0; nt < 4; nt++)
#pragma unroll
                for (int mt = 0; mt < 2; mt++) mma16816(acc[mt][nt], aH[mt], &bH[nt * 2]);
#pragma unroll
            for (int nt = 0; nt < 4; nt++)
#pragma unroll
                for (int mt = 0; mt < 2; mt++) mma16816(acc[mt][nt], aH[mt], &bL[nt * 2]);
        }
        if (c < 6) CP_WAIT1();
        else if (c == 6) CP_WAIT0();
        __syncthreads();
    }

    const float scale = g_scale[0];
#pragma unroll
    for (int nt = 0; nt < 4; nt++) {
        const int col = n0 + wn + nt * 8 + 2 * tq;
        const float b0 = __ldg(&bias[col]), b1 = __ldg(&bias[col + 1]);
#pragma unroll
        for (int mt = 0; mt < 2; mt++) {
            const int row = m0 + wm + mt * 16 + g;
            float2 o0, o1;
            o0.x = tanh_acc(scale * (acc[mt][nt][0] + b0));
            o0.y = tanh_acc(scale * (acc[mt][nt][1] + b1));
            o1.x = tanh_acc(scale * (acc[mt][nt][2] + b0));
            o1.y = tanh_acc(scale * (acc[mt][nt][3] + b1));
            *(float2*)(out + (size_t)row * 256 + col)       = o0;
            *(float2*)(out + (size_t)(row + 8) * 256 + col) = o1;
        }
    }
}

extern "C" void kernel_launch(void* const* d_in, const int* in_sizes, int n_in,
                              void* d_out, int out_size) {
    const float* x = nullptr; const float* W = nullptr; const float* b = nullptr;
    for (int i = 0; i < n_in; i++) {
        const int s = in_sizes[i];
        if (s == 256) b = (const float*)d_in[i];
        else if (s == 131072) W = (const float*)d_in[i];
        else x = (const float*)d_in[i];
    }
    float* out = (float*)d_out;
    cudaFuncSetAttribute(sigma_kernel, cudaFuncAttributeMaxDynamicSharedMemorySize, SIG_SMEM);
    cudaFuncSetAttribute(gemm_mma_kernel, cudaFuncAttributeMaxDynamicSharedMemorySize, GEMM_SMEM);

    const int main_elems = M_TOTAL * 256;
    const int tail = (out_size > main_elems) ? (out_size - main_elems) : 0;
    split_kernel<<<2180, 256>>>(W, x, out + main_elems, tail);
    sigma_kernel<<<64, 1024, SIG_SMEM>>>(W);
    gemm_mma_kernel<<<dim3(4, 512), 256, GEMM_SMEM>>>(b, out);
}